// round 1
// baseline (speedup 1.0000x reference)
#include <cuda_runtime.h>
#include <math.h>

#define NB 8
#define NC 512
#define NL 1024
#define NH 8
#define DH 64
#define WIN 4
#define NT 9   // 2*WIN+1

// Scratch (allocation-free contract: __device__ globals). Layout (b,h,d,l) == (b, c, l).
__device__ float g_q[NB * NC * NL];
__device__ float g_k[NB * NC * NL];
__device__ float g_v[NB * NC * NL];
__device__ float g_t[NB * NC * NL];

// ---------------------------------------------------------------------------
// Y[b, m, n] = (sum_c W[m,c] * X[b,c,n] + bias[m]) * alpha
// M = 512, N = 1024, K = 512. 128x128 block tile, 256 threads, 8x8 per thread.
// ---------------------------------------------------------------------------
__global__ __launch_bounds__(256) void gemm_cl(
    const float* __restrict__ Wm, const float* __restrict__ bias,
    const float* __restrict__ X, float* __restrict__ Y, float alpha)
{
    __shared__ float As[8][132];   // As[k][m]
    __shared__ float Bs[8][132];   // Bs[k][n]

    const int b  = blockIdx.z;
    const int m0 = blockIdx.y * 128;
    const int n0 = blockIdx.x * 128;
    const float* Xb = X + (size_t)b * NC * NL;
    float*       Yb = Y + (size_t)b * NC * NL;

    const int t  = threadIdx.x;
    const int tx = t & 15, ty = t >> 4;

    // A-tile load mapping: thread -> one float4 of W
    const int am = t >> 1;           // 0..127 (row within tile)
    const int ak = (t & 1) * 4;      // 0 or 4
    // B-tile load mapping
    const int bk = t >> 5;           // 0..7
    const int bn = (t & 31) * 4;     // 0..124

    float acc[8][8];
#pragma unroll
    for (int i = 0; i < 8; i++)
#pragma unroll
        for (int j = 0; j < 8; j++) acc[i][j] = 0.f;

    for (int k0 = 0; k0 < NC; k0 += 8) {
        float4 a4 = *(const float4*)(Wm + (size_t)(m0 + am) * NC + k0 + ak);
        As[ak + 0][am] = a4.x; As[ak + 1][am] = a4.y;
        As[ak + 2][am] = a4.z; As[ak + 3][am] = a4.w;
        *(float4*)&Bs[bk][bn] = *(const float4*)(Xb + (size_t)(k0 + bk) * NL + n0 + bn);
        __syncthreads();

#pragma unroll
        for (int kk = 0; kk < 8; kk++) {
            float4 x0 = *(const float4*)&As[kk][ty * 8];
            float4 x1 = *(const float4*)&As[kk][ty * 8 + 4];
            float4 y0 = *(const float4*)&Bs[kk][tx * 4];
            float4 y1 = *(const float4*)&Bs[kk][64 + tx * 4];
            float a[8]  = {x0.x, x0.y, x0.z, x0.w, x1.x, x1.y, x1.z, x1.w};
            float bb[8] = {y0.x, y0.y, y0.z, y0.w, y1.x, y1.y, y1.z, y1.w};
#pragma unroll
            for (int i = 0; i < 8; i++)
#pragma unroll
                for (int j = 0; j < 8; j++)
                    acc[i][j] = fmaf(a[i], bb[j], acc[i][j]);
        }
        __syncthreads();
    }

#pragma unroll
    for (int i = 0; i < 8; i++) {
        int m = m0 + ty * 8 + i;
        float bv = bias[m];
        float4 s0, s1;
        s0.x = (acc[i][0] + bv) * alpha; s0.y = (acc[i][1] + bv) * alpha;
        s0.z = (acc[i][2] + bv) * alpha; s0.w = (acc[i][3] + bv) * alpha;
        s1.x = (acc[i][4] + bv) * alpha; s1.y = (acc[i][5] + bv) * alpha;
        s1.z = (acc[i][6] + bv) * alpha; s1.w = (acc[i][7] + bv) * alpha;
        *(float4*)(Yb + (size_t)m * NL + n0 + tx * 4)      = s0;
        *(float4*)(Yb + (size_t)m * NL + n0 + 64 + tx * 4) = s1;
    }
}

// ---------------------------------------------------------------------------
// Flash attention per (b,h): 64-row Q tiles, 64-col K/V tiles, online softmax,
// band-limited relative-position terms (rel_k via precomputed q·erk table,
// rel_v via rescaled 9-slot probability accumulator).
// q/k/v layout: (bh, d, l). Output to (bh, d, l) == (b, c, l).
// ---------------------------------------------------------------------------
__global__ __launch_bounds__(256) void attn_kernel(
    const float* __restrict__ erk, const float* __restrict__ erv)
{
    extern __shared__ float sm[];
    float (*Qs)[65]  = (float(*)[65])(sm);
    float (*Ks)[65]  = (float(*)[65])(sm + 64 * 65);
    float (*Vs)[65]  = (float(*)[65])(sm + 2 * 64 * 65);
    float (*Ps)[65]  = (float(*)[65])(sm + 3 * 64 * 65);
    float (*rq)[NT]  = (float(*)[NT])(sm + 4 * 64 * 65);
    float (*arel)[NT]= (float(*)[NT])(sm + 4 * 64 * 65 + 64 * NT);
    float* fsc       = sm + 4 * 64 * 65 + 2 * 64 * NT;
    float (*ervs)[DH]= (float(*)[DH])(sm + 4 * 64 * 65 + 2 * 64 * NT + 64);

    const int bh = blockIdx.y;
    const int i0 = blockIdx.x * 64;
    const float* qb = g_q + (size_t)bh * DH * NL;
    const float* kb = g_k + (size_t)bh * DH * NL;
    const float* vb = g_v + (size_t)bh * DH * NL;
    float*       ob = g_t + (size_t)bh * DH * NL;

    const int t  = threadIdx.x;
    const int tx = t & 15, ty = t >> 4;
    const int r0 = ty * 4, c0 = tx * 4;

    // Load Q tile (coalesced over l), Qs[l][d]
    for (int e = t; e < 64 * 64; e += 256) {
        int d = e >> 6, l = e & 63;
        Qs[l][d] = qb[d * NL + i0 + l];
    }
    for (int e = t; e < NT * DH; e += 256) ((float*)ervs)[e] = erv[e];
    __syncthreads();

    // rq[r][t] = sum_d q[r][d] * erk[t][d]; init arel = 0
    for (int e = t; e < 64 * NT; e += 256) {
        int r = e / NT, tt = e % NT;
        float s = 0.f;
#pragma unroll 16
        for (int d = 0; d < DH; d++) s = fmaf(Qs[r][d], erk[tt * DH + d], s);
        rq[r][tt] = s;
        arel[r][tt] = 0.f;
    }

    float m_i[4], l_i[4], o[4][4];
#pragma unroll
    for (int i = 0; i < 4; i++) {
        m_i[i] = -INFINITY; l_i[i] = 0.f;
#pragma unroll
        for (int j = 0; j < 4; j++) o[i][j] = 0.f;
    }

    for (int j0 = 0; j0 < NL; j0 += 64) {
        // Load K/V tiles
        for (int e = t; e < 64 * 64; e += 256) {
            int d = e >> 6, l = e & 63;
            Ks[l][d] = kb[d * NL + j0 + l];
            Vs[l][d] = vb[d * NL + j0 + l];
        }
        __syncthreads();

        // S = Q K^T (4x4 per thread)
        float s[4][4];
#pragma unroll
        for (int i = 0; i < 4; i++)
#pragma unroll
            for (int j = 0; j < 4; j++) s[i][j] = 0.f;

#pragma unroll 8
        for (int d = 0; d < DH; d++) {
            float a0 = Qs[r0 + 0][d], a1 = Qs[r0 + 1][d];
            float a2 = Qs[r0 + 2][d], a3 = Qs[r0 + 3][d];
            float b0 = Ks[c0 + 0][d], b1 = Ks[c0 + 1][d];
            float b2 = Ks[c0 + 2][d], b3 = Ks[c0 + 3][d];
            s[0][0] = fmaf(a0, b0, s[0][0]); s[0][1] = fmaf(a0, b1, s[0][1]);
            s[0][2] = fmaf(a0, b2, s[0][2]); s[0][3] = fmaf(a0, b3, s[0][3]);
            s[1][0] = fmaf(a1, b0, s[1][0]); s[1][1] = fmaf(a1, b1, s[1][1]);
            s[1][2] = fmaf(a1, b2, s[1][2]); s[1][3] = fmaf(a1, b3, s[1][3]);
            s[2][0] = fmaf(a2, b0, s[2][0]); s[2][1] = fmaf(a2, b1, s[2][1]);
            s[2][2] = fmaf(a2, b2, s[2][2]); s[2][3] = fmaf(a2, b3, s[2][3]);
            s[3][0] = fmaf(a3, b0, s[3][0]); s[3][1] = fmaf(a3, b1, s[3][1]);
            s[3][2] = fmaf(a3, b2, s[3][2]); s[3][3] = fmaf(a3, b3, s[3][3]);
        }

        // rel_k band addition: t = (j - i) + WIN in [0, NT)
#pragma unroll
        for (int i = 0; i < 4; i++) {
            int base = (j0 + c0) - (i0 + r0 + i) + WIN;
#pragma unroll
            for (int j = 0; j < 4; j++) {
                int tt = base + j;
                if (tt >= 0 && tt < NT) s[i][j] += rq[r0 + i][tt];
            }
        }

        // Online softmax update (rows grouped over 16-lane shuffle sets)
#pragma unroll
        for (int i = 0; i < 4; i++) {
            float mx = fmaxf(fmaxf(s[i][0], s[i][1]), fmaxf(s[i][2], s[i][3]));
#pragma unroll
            for (int off = 8; off; off >>= 1)
                mx = fmaxf(mx, __shfl_xor_sync(0xffffffffu, mx, off));
            float mnew = fmaxf(m_i[i], mx);
            float f = __expf(m_i[i] - mnew);
            float rs = 0.f;
#pragma unroll
            for (int j = 0; j < 4; j++) { s[i][j] = __expf(s[i][j] - mnew); rs += s[i][j]; }
#pragma unroll
            for (int off = 8; off; off >>= 1)
                rs += __shfl_xor_sync(0xffffffffu, rs, off);
            l_i[i] = l_i[i] * f + rs;
            m_i[i] = mnew;
#pragma unroll
            for (int j = 0; j < 4; j++) o[i][j] *= f;
#pragma unroll
            for (int j = 0; j < 4; j++) Ps[r0 + i][c0 + j] = s[i][j];
            if (tx == 0) fsc[r0 + i] = f;
        }
        __syncthreads();

        // Band probability accumulator for rel_v (rescale every tile)
        for (int e = t; e < 64 * NT; e += 256) {
            int r = e / NT, tt = e % NT;
            int jg = (i0 + r) + tt - WIN;
            float a = arel[r][tt] * fsc[r];
            if (jg >= j0 && jg < j0 + 64) a += Ps[r][jg - j0];
            arel[r][tt] = a;
        }

        // O += P V
#pragma unroll 8
        for (int c = 0; c < 64; c++) {
            float p0 = Ps[r0 + 0][c], p1 = Ps[r0 + 1][c];
            float p2 = Ps[r0 + 2][c], p3 = Ps[r0 + 3][c];
            float v0 = Vs[c][c0 + 0], v1 = Vs[c][c0 + 1];
            float v2 = Vs[c][c0 + 2], v3 = Vs[c][c0 + 3];
            o[0][0] = fmaf(p0, v0, o[0][0]); o[0][1] = fmaf(p0, v1, o[0][1]);
            o[0][2] = fmaf(p0, v2, o[0][2]); o[0][3] = fmaf(p0, v3, o[0][3]);
            o[1][0] = fmaf(p1, v0, o[1][0]); o[1][1] = fmaf(p1, v1, o[1][1]);
            o[1][2] = fmaf(p1, v2, o[1][2]); o[1][3] = fmaf(p1, v3, o[1][3]);
            o[2][0] = fmaf(p2, v0, o[2][0]); o[2][1] = fmaf(p2, v1, o[2][1]);
            o[2][2] = fmaf(p2, v2, o[2][2]); o[2][3] = fmaf(p2, v3, o[2][3]);
            o[3][0] = fmaf(p3, v0, o[3][0]); o[3][1] = fmaf(p3, v1, o[3][1]);
            o[3][2] = fmaf(p3, v2, o[3][2]); o[3][3] = fmaf(p3, v3, o[3][3]);
        }
        __syncthreads();
    }

    // Epilogue: add rel_v contribution, normalize, transpose through smem,
    // store coalesced along l into (bh, d, l).
#pragma unroll
    for (int i = 0; i < 4; i++) {
        float inv = 1.f / l_i[i];
#pragma unroll
        for (int j = 0; j < 4; j++) {
            float rv = 0.f;
#pragma unroll
            for (int tt = 0; tt < NT; tt++)
                rv = fmaf(arel[r0 + i][tt], ervs[tt][c0 + j], rv);
            Ks[c0 + j][r0 + i] = (o[i][j] + rv) * inv;   // Ks reused as [d][l]
        }
    }
    __syncthreads();
    for (int e = t; e < 64 * 64; e += 256) {
        int d = e >> 6, l = e & 63;
        ob[d * NL + i0 + l] = Ks[d][l];
    }
}

// ---------------------------------------------------------------------------
extern "C" void kernel_launch(void* const* d_in, const int* in_sizes, int n_in,
                              void* d_out, int out_size)
{
    const float* x   = (const float*)d_in[0];
    const float* Wq  = (const float*)d_in[1];
    const float* bq  = (const float*)d_in[2];
    const float* Wk  = (const float*)d_in[3];
    const float* bk  = (const float*)d_in[4];
    const float* Wv  = (const float*)d_in[5];
    const float* bv  = (const float*)d_in[6];
    const float* Wo  = (const float*)d_in[7];
    const float* bo  = (const float*)d_in[8];
    const float* erk = (const float*)d_in[9];
    const float* erv = (const float*)d_in[10];
    float* out = (float*)d_out;

    float *gq, *gk, *gv, *gt;
    cudaGetSymbolAddress((void**)&gq, g_q);
    cudaGetSymbolAddress((void**)&gk, g_k);
    cudaGetSymbolAddress((void**)&gv, g_v);
    cudaGetSymbolAddress((void**)&gt, g_t);

    const int attn_smem = (4 * 64 * 65 + 2 * 64 * NT + 64 + NT * DH) * 4;
    cudaFuncSetAttribute(attn_kernel,
                         cudaFuncAttributeMaxDynamicSharedMemorySize, attn_smem);

    dim3 gp(NL / 128, NC / 128, NB);   // (8,4,8)
    const float scale = 0.125f;        // Dh^-0.5, folded into Q projection

    gemm_cl<<<gp, 256>>>(Wq, bq, x, gq, scale);
    gemm_cl<<<gp, 256>>>(Wk, bk, x, gk, 1.f);
    gemm_cl<<<gp, 256>>>(Wv, bv, x, gv, 1.f);

    dim3 ga(NL / 64, NB * NH);         // (16, 64)
    attn_kernel<<<ga, 256, attn_smem>>>(erk, erv);

    gemm_cl<<<gp, 256>>>(Wo, bo, gt, out, 1.f);
}

// round 2
// speedup vs baseline: 1.0785x; 1.0785x over previous
#include <cuda_runtime.h>
#include <math.h>
#include <stdint.h>

#define NB 8
#define NC 512
#define NL 1024
#define NH 8
#define DH 64
#define WIN 4
#define NT 9   // 2*WIN+1

// Scratch (allocation-free contract). Layout (b,h,d,l) == (b, c, l).
__device__ float g_q[NB * NC * NL];
__device__ float g_k[NB * NC * NL];
__device__ float g_v[NB * NC * NL];
__device__ float g_t[NB * NC * NL];

__device__ __forceinline__ void cp16(uint32_t dst, const void* src) {
    asm volatile("cp.async.cg.shared.global [%0], [%1], 16;" :: "r"(dst), "l"(src));
}
__device__ __forceinline__ void cp_commit() { asm volatile("cp.async.commit_group;"); }
__device__ __forceinline__ void cp_wait_all() { asm volatile("cp.async.wait_group 0;" ::: "memory"); }

// ---------------------------------------------------------------------------
// Y[b, m, n] = (sum_c W[m,c] * X[b,c,n] + bias[m]) * alpha
// ---------------------------------------------------------------------------
__global__ __launch_bounds__(256) void gemm_cl(
    const float* __restrict__ Wm, const float* __restrict__ bias,
    const float* __restrict__ X, float* __restrict__ Y, float alpha)
{
    __shared__ float As[8][132];   // As[k][m]
    __shared__ float Bs[8][132];   // Bs[k][n]

    const int b  = blockIdx.z;
    const int m0 = blockIdx.y * 128;
    const int n0 = blockIdx.x * 128;
    const float* Xb = X + (size_t)b * NC * NL;
    float*       Yb = Y + (size_t)b * NC * NL;

    const int t  = threadIdx.x;
    const int tx = t & 15, ty = t >> 4;

    const int am = t >> 1;
    const int ak = (t & 1) * 4;
    const int bk = t >> 5;
    const int bn = (t & 31) * 4;

    float acc[8][8];
#pragma unroll
    for (int i = 0; i < 8; i++)
#pragma unroll
        for (int j = 0; j < 8; j++) acc[i][j] = 0.f;

    for (int k0 = 0; k0 < NC; k0 += 8) {
        float4 a4 = *(const float4*)(Wm + (size_t)(m0 + am) * NC + k0 + ak);
        As[ak + 0][am] = a4.x; As[ak + 1][am] = a4.y;
        As[ak + 2][am] = a4.z; As[ak + 3][am] = a4.w;
        *(float4*)&Bs[bk][bn] = *(const float4*)(Xb + (size_t)(k0 + bk) * NL + n0 + bn);
        __syncthreads();

#pragma unroll
        for (int kk = 0; kk < 8; kk++) {
            float4 x0 = *(const float4*)&As[kk][ty * 8];
            float4 x1 = *(const float4*)&As[kk][ty * 8 + 4];
            float4 y0 = *(const float4*)&Bs[kk][tx * 4];
            float4 y1 = *(const float4*)&Bs[kk][64 + tx * 4];
            float a[8]  = {x0.x, x0.y, x0.z, x0.w, x1.x, x1.y, x1.z, x1.w};
            float bb[8] = {y0.x, y0.y, y0.z, y0.w, y1.x, y1.y, y1.z, y1.w};
#pragma unroll
            for (int i = 0; i < 8; i++)
#pragma unroll
                for (int j = 0; j < 8; j++)
                    acc[i][j] = fmaf(a[i], bb[j], acc[i][j]);
        }
        __syncthreads();
    }

#pragma unroll
    for (int i = 0; i < 8; i++) {
        int m = m0 + ty * 8 + i;
        float bv = bias[m];
        float4 s0, s1;
        s0.x = (acc[i][0] + bv) * alpha; s0.y = (acc[i][1] + bv) * alpha;
        s0.z = (acc[i][2] + bv) * alpha; s0.w = (acc[i][3] + bv) * alpha;
        s1.x = (acc[i][4] + bv) * alpha; s1.y = (acc[i][5] + bv) * alpha;
        s1.z = (acc[i][6] + bv) * alpha; s1.w = (acc[i][7] + bv) * alpha;
        *(float4*)(Yb + (size_t)m * NL + n0 + tx * 4)      = s0;
        *(float4*)(Yb + (size_t)m * NL + n0 + 64 + tx * 4) = s1;
    }
}

// ---------------------------------------------------------------------------
// Flash attention per (b,h). 64x64 tiles, vectorized smem, cp.async K pipe.
// K smem: [d][l] pad 64. Q smem: [d][l] pad 64. V smem: [l][d] pad 68.
// P smem: transposed [c][r] pad 68.
// ---------------------------------------------------------------------------
#define KPAD 64
#define VPAD 68
#define PPAD 68

__global__ __launch_bounds__(256, 2) void attn_kernel(
    const float* __restrict__ erk, const float* __restrict__ erv)
{
    extern __shared__ float sm[];
    float* Kb   = sm;                       // 2 * 64*64 = 8192
    float* Vs   = sm + 8192;                // 64*68 = 4352
    float* Qs   = Vs + 4352;                // 64*64 = 4096
    float* Ps   = Qs + 4096;                // 64*68 = 4352
    float* rq   = Ps + 4352;                // 64*NT = 576
    float* arel = rq + 576;                 // 576
    float* fsc  = arel + 576;               // 64
    float* ervs = fsc + 64;                 // NT*64 = 576

    const int bh = blockIdx.y;
    const int i0 = blockIdx.x * 64;
    const float* qb = g_q + (size_t)bh * DH * NL;
    const float* kb = g_k + (size_t)bh * DH * NL;
    const float* vb = g_v + (size_t)bh * DH * NL;
    float*       ob = g_t + (size_t)bh * DH * NL;

    const int t  = threadIdx.x;
    const int tx = t & 15, ty = t >> 4;
    const int r0 = ty * 4, c0 = tx * 4;

    // Prefetch K tile 0 via cp.async (direct copy, [d][l])
#pragma unroll
    for (int it = 0; it < 4; it++) {
        int e = t + it * 256, d = e >> 4, l4 = (e & 15) * 4;
        cp16((uint32_t)__cvta_generic_to_shared(Kb + d * KPAD + l4),
             kb + (size_t)d * NL + l4);
    }
    cp_commit();

    // Load Q tile [d][l] (float4, coalesced)
#pragma unroll
    for (int it = 0; it < 4; it++) {
        int e = t + it * 256, d = e >> 4, l4 = (e & 15) * 4;
        *(float4*)(Qs + d * KPAD + l4) = *(const float4*)(qb + (size_t)d * NL + i0 + l4);
    }
    for (int e = t; e < NT * DH; e += 256) ervs[e] = erv[e];
    __syncthreads();

    // rq[r*NT+tt] = sum_d q[r][d] * erk[tt][d]
    for (int e = t; e < 64 * NT; e += 256) {
        int r = e / NT, tt = e % NT;
        float s = 0.f;
#pragma unroll 16
        for (int d = 0; d < DH; d++) s = fmaf(Qs[d * KPAD + r], erk[tt * DH + d], s);
        rq[e] = s;
        arel[e] = 0.f;
    }

    float m_i[4], l_i[4], o[4][4];
#pragma unroll
    for (int i = 0; i < 4; i++) {
        m_i[i] = -INFINITY; l_i[i] = 0.f;
#pragma unroll
        for (int j = 0; j < 4; j++) o[i][j] = 0.f;
    }

    int buf = 0;
    for (int jt = 0; jt < 16; jt++, buf ^= 1) {
        const int j0 = jt * 64;
        cp_wait_all();
        __syncthreads();

        // Prefetch next K tile into the other buffer
        if (jt + 1 < 16) {
            const float* kn = kb + j0 + 64;
#pragma unroll
            for (int it = 0; it < 4; it++) {
                int e = t + it * 256, d = e >> 4, l4 = (e & 15) * 4;
                cp16((uint32_t)__cvta_generic_to_shared(Kb + (buf ^ 1) * 4096 + d * KPAD + l4),
                     kn + (size_t)d * NL + l4);
            }
            cp_commit();
        }

        // Issue V loads early (latency hidden behind S compute).
        // Thread grabs 4 d-rows at one l -> later one STS.128 along d.
        float vr[4][4];
#pragma unroll
        for (int it = 0; it < 4; it++) {
            int e = t + it * 256, l = e & 63, d4 = (e >> 6) * 4;
            const float* vp = vb + (size_t)d4 * NL + j0 + l;
#pragma unroll
            for (int k = 0; k < 4; k++) vr[it][k] = __ldg(vp + (size_t)k * NL);
        }

        // S = Q K^T, 4x4 per thread, vectorized LDS
        const float* Kt = Kb + buf * 4096;
        float s4[4][4];
#pragma unroll
        for (int i = 0; i < 4; i++)
#pragma unroll
            for (int j = 0; j < 4; j++) s4[i][j] = 0.f;

#pragma unroll 4
        for (int d = 0; d < DH; d++) {
            float4 q = *(const float4*)(Qs + d * KPAD + r0);
            float4 k = *(const float4*)(Kt + d * KPAD + c0);
            s4[0][0] = fmaf(q.x, k.x, s4[0][0]); s4[0][1] = fmaf(q.x, k.y, s4[0][1]);
            s4[0][2] = fmaf(q.x, k.z, s4[0][2]); s4[0][3] = fmaf(q.x, k.w, s4[0][3]);
            s4[1][0] = fmaf(q.y, k.x, s4[1][0]); s4[1][1] = fmaf(q.y, k.y, s4[1][1]);
            s4[1][2] = fmaf(q.y, k.z, s4[1][2]); s4[1][3] = fmaf(q.y, k.w, s4[1][3]);
            s4[2][0] = fmaf(q.z, k.x, s4[2][0]); s4[2][1] = fmaf(q.z, k.y, s4[2][1]);
            s4[2][2] = fmaf(q.z, k.z, s4[2][2]); s4[2][3] = fmaf(q.z, k.w, s4[2][3]);
            s4[3][0] = fmaf(q.w, k.x, s4[3][0]); s4[3][1] = fmaf(q.w, k.y, s4[3][1]);
            s4[3][2] = fmaf(q.w, k.z, s4[3][2]); s4[3][3] = fmaf(q.w, k.w, s4[3][3]);
        }

        // rel_k band: tt = (j - i) + WIN in [0, NT)
#pragma unroll
        for (int i = 0; i < 4; i++) {
            int base = (j0 + c0) - (i0 + r0 + i) + WIN;
#pragma unroll
            for (int j = 0; j < 4; j++) {
                int tt = base + j;
                if (tt >= 0 && tt < NT) s4[i][j] += rq[(r0 + i) * NT + tt];
            }
        }

        // Online softmax
#pragma unroll
        for (int i = 0; i < 4; i++) {
            float mx = fmaxf(fmaxf(s4[i][0], s4[i][1]), fmaxf(s4[i][2], s4[i][3]));
#pragma unroll
            for (int off = 8; off; off >>= 1)
                mx = fmaxf(mx, __shfl_xor_sync(0xffffffffu, mx, off));
            float mnew = fmaxf(m_i[i], mx);
            float f = __expf(m_i[i] - mnew);
            float rs = 0.f;
#pragma unroll
            for (int j = 0; j < 4; j++) { s4[i][j] = __expf(s4[i][j] - mnew); rs += s4[i][j]; }
#pragma unroll
            for (int off = 8; off; off >>= 1)
                rs += __shfl_xor_sync(0xffffffffu, rs, off);
            l_i[i] = l_i[i] * f + rs;
            m_i[i] = mnew;
#pragma unroll
            for (int j = 0; j < 4; j++) o[i][j] *= f;
            if (tx == 0) fsc[r0 + i] = f;
        }

        // Store P transposed [c][r] via float4
#pragma unroll
        for (int j = 0; j < 4; j++) {
            float4 pj = make_float4(s4[0][j], s4[1][j], s4[2][j], s4[3][j]);
            *(float4*)(Ps + (c0 + j) * PPAD + r0) = pj;
        }

        // Store V transposed [l][d] via STS.128 along d (conflict-free)
#pragma unroll
        for (int it = 0; it < 4; it++) {
            int e = t + it * 256, l = e & 63, d4 = (e >> 6) * 4;
            *(float4*)(Vs + l * VPAD + d4) =
                make_float4(vr[it][0], vr[it][1], vr[it][2], vr[it][3]);
        }
        __syncthreads();

        // Band probability accumulator for rel_v
        for (int e = t; e < 64 * NT; e += 256) {
            int r = e / NT, tt = e % NT;
            int jg = (i0 + r) + tt - WIN;
            float a = arel[e] * fsc[r];
            if (jg >= j0 && jg < j0 + 64) a += Ps[(jg - j0) * PPAD + r];
            arel[e] = a;
        }

        // O += P V, vectorized
#pragma unroll 4
        for (int c = 0; c < 64; c++) {
            float4 p = *(const float4*)(Ps + c * PPAD + r0);   // broadcast
            float4 v = *(const float4*)(Vs + c * VPAD + c0);   // conflict-free
            o[0][0] = fmaf(p.x, v.x, o[0][0]); o[0][1] = fmaf(p.x, v.y, o[0][1]);
            o[0][2] = fmaf(p.x, v.z, o[0][2]); o[0][3] = fmaf(p.x, v.w, o[0][3]);
            o[1][0] = fmaf(p.y, v.x, o[1][0]); o[1][1] = fmaf(p.y, v.y, o[1][1]);
            o[1][2] = fmaf(p.y, v.z, o[1][2]); o[1][3] = fmaf(p.y, v.w, o[1][3]);
            o[2][0] = fmaf(p.z, v.x, o[2][0]); o[2][1] = fmaf(p.z, v.y, o[2][1]);
            o[2][2] = fmaf(p.z, v.z, o[2][2]); o[2][3] = fmaf(p.z, v.w, o[2][3]);
            o[3][0] = fmaf(p.w, v.x, o[3][0]); o[3][1] = fmaf(p.w, v.y, o[3][1]);
            o[3][2] = fmaf(p.w, v.z, o[3][2]); o[3][3] = fmaf(p.w, v.w, o[3][3]);
        }
        __syncthreads();
    }

    // Epilogue: rel_v add, normalize, transpose through Ps as [d][l]
#pragma unroll
    for (int i = 0; i < 4; i++) {
        float inv = 1.f / l_i[i];
#pragma unroll
        for (int j = 0; j < 4; j++) {
            float rv = 0.f;
#pragma unroll
            for (int tt = 0; tt < NT; tt++)
                rv = fmaf(arel[(r0 + i) * NT + tt], ervs[tt * DH + c0 + j], rv);
            Ps[(c0 + j) * PPAD + (r0 + i)] = (o[i][j] + rv) * inv;
        }
    }
    __syncthreads();
    for (int e = t; e < 64 * 64; e += 256) {
        int d = e >> 6, l = e & 63;
        ob[(size_t)d * NL + i0 + l] = Ps[d * PPAD + l];
    }
}

// ---------------------------------------------------------------------------
extern "C" void kernel_launch(void* const* d_in, const int* in_sizes, int n_in,
                              void* d_out, int out_size)
{
    const float* x   = (const float*)d_in[0];
    const float* Wq  = (const float*)d_in[1];
    const float* bq  = (const float*)d_in[2];
    const float* Wk  = (const float*)d_in[3];
    const float* bk  = (const float*)d_in[4];
    const float* Wv  = (const float*)d_in[5];
    const float* bv  = (const float*)d_in[6];
    const float* Wo  = (const float*)d_in[7];
    const float* bo  = (const float*)d_in[8];
    const float* erk = (const float*)d_in[9];
    const float* erv = (const float*)d_in[10];
    float* out = (float*)d_out;

    float *gq, *gk, *gv, *gt;
    cudaGetSymbolAddress((void**)&gq, g_q);
    cudaGetSymbolAddress((void**)&gk, g_k);
    cudaGetSymbolAddress((void**)&gv, g_v);
    cudaGetSymbolAddress((void**)&gt, g_t);

    const int attn_smem = (8192 + 4352 + 4096 + 4352 + 576 + 576 + 64 + 576) * 4;
    cudaFuncSetAttribute(attn_kernel,
                         cudaFuncAttributeMaxDynamicSharedMemorySize, attn_smem);

    dim3 gp(NL / 128, NC / 128, NB);
    const float scale = 0.125f;   // Dh^-0.5 folded into Q projection

    gemm_cl<<<gp, 256>>>(Wq, bq, x, gq, scale);
    gemm_cl<<<gp, 256>>>(Wk, bk, x, gk, 1.f);
    gemm_cl<<<gp, 256>>>(Wv, bv, x, gv, 1.f);

    dim3 ga(NL / 64, NB * NH);
    attn_kernel<<<ga, 256, attn_smem>>>(erk, erv);

    gemm_cl<<<gp, 256>>>(Wo, bo, gt, out, 1.f);
}

// round 4
// speedup vs baseline: 1.4271x; 1.3232x over previous
#include <cuda_runtime.h>
#include <cuda_bf16.h>
#include <math.h>
#include <stdint.h>

#define NB 8
#define NC 512
#define NL 1024
#define NH 8
#define DH 64
#define WIN 4
#define NT 9   // 2*WIN+1

// Scratch (allocation-free contract).
__device__ float g_q[NB * NC * NL];
__device__ float g_k[NB * NC * NL];
__device__ float g_v[NB * NC * NL];
__device__ __nv_bfloat16 g_xT_hi[NB * NL * NC];   // x transposed [b][l][c]
__device__ __nv_bfloat16 g_xT_lo[NB * NL * NC];
__device__ __nv_bfloat16 g_tT_hi[NB * NL * NC];   // attn out transposed [b][l][c]
__device__ __nv_bfloat16 g_tT_lo[NB * NL * NC];
__device__ __nv_bfloat16 g_W_hi[4 * NC * NC];     // Wq*0.125, Wk, Wv, Wo
__device__ __nv_bfloat16 g_W_lo[4 * NC * NC];

// ---------------- PTX helpers (arch-portable: sm_80+ features only) --------
__device__ __forceinline__ void cp16(uint32_t dst, const void* src) {
    asm volatile("cp.async.cg.shared.global [%0], [%1], 16;" :: "r"(dst), "l"(src));
}
__device__ __forceinline__ void cp_commit() { asm volatile("cp.async.commit_group;"); }
__device__ __forceinline__ void cp_wait0() { asm volatile("cp.async.wait_group 0;" ::: "memory"); }
__device__ __forceinline__ void cp_wait1() { asm volatile("cp.async.wait_group 1;" ::: "memory"); }

__device__ __forceinline__ uint32_t smem_u32(const void* p) {
    uint32_t a;
    asm("{ .reg .u64 t; cvta.to.shared.u64 t, %1; cvt.u32.u64 %0, t; }" : "=r"(a) : "l"(p));
    return a;
}
__device__ __forceinline__ void ld4(uint32_t* r, uint32_t addr) {
    asm volatile("ldmatrix.sync.aligned.m8n8.x4.shared.b16 {%0,%1,%2,%3}, [%4];"
                 : "=r"(r[0]), "=r"(r[1]), "=r"(r[2]), "=r"(r[3]) : "r"(addr));
}
__device__ __forceinline__ void mma_bf16(float* d, const uint32_t* a, const uint32_t* b) {
    asm volatile(
        "mma.sync.aligned.m16n8k16.row.col.f32.bf16.bf16.f32 "
        "{%0,%1,%2,%3}, {%4,%5,%6,%7}, {%8,%9}, {%0,%1,%2,%3};"
        : "+f"(d[0]), "+f"(d[1]), "+f"(d[2]), "+f"(d[3])
        : "r"(a[0]), "r"(a[1]), "r"(a[2]), "r"(a[3]), "r"(b[0]), "r"(b[1]));
}

// ---------------------------------------------------------------------------
// Prep: split 4 weight matrices into bf16 hi/lo (scale folded into Wq).
// ---------------------------------------------------------------------------
__global__ void split_w(const float* __restrict__ w0, const float* __restrict__ w1,
                        const float* __restrict__ w2, const float* __restrict__ w3)
{
    int widx = blockIdx.y;
    const float* w = widx == 0 ? w0 : widx == 1 ? w1 : widx == 2 ? w2 : w3;
    float alpha = (widx == 0) ? 0.125f : 1.f;
    int e = blockIdx.x * 256 + threadIdx.x;
    float v = w[e] * alpha;
    __nv_bfloat16 hi = __float2bfloat16(v);
    __nv_bfloat16 lo = __float2bfloat16(v - __bfloat162float(hi));
    g_W_hi[widx * NC * NC + e] = hi;
    g_W_lo[widx * NC * NC + e] = lo;
}

// ---------------------------------------------------------------------------
// Prep: transpose x (b,c,l) -> xT (b,l,c) as bf16 hi/lo.
// ---------------------------------------------------------------------------
__global__ __launch_bounds__(256) void split_xT(const float* __restrict__ x)
{
    __shared__ float tile[32][33];
    int b = blockIdx.z, c0 = blockIdx.y * 32, l0 = blockIdx.x * 32;
    const float* xb = x + ((size_t)b * NC + c0) * NL + l0;
    int tx = threadIdx.x & 31, ty = threadIdx.x >> 5;
#pragma unroll
    for (int i = 0; i < 4; i++)
        tile[ty + i * 8][tx] = xb[(size_t)(ty + i * 8) * NL + tx];
    __syncthreads();
    size_t ob = ((size_t)b * NL + l0) * NC + c0;
#pragma unroll
    for (int i = 0; i < 4; i++) {
        int r = ty + i * 8;
        float v = tile[tx][r];
        __nv_bfloat16 hi = __float2bfloat16(v);
        __nv_bfloat16 lo = __float2bfloat16(v - __bfloat162float(hi));
        g_xT_hi[ob + (size_t)r * NC + tx] = hi;
        g_xT_lo[ob + (size_t)r * NC + tx] = lo;
    }
}

// ---------------------------------------------------------------------------
// mma.sync bf16x2 GEMM: Y[b,m,n] = sum_k W[m,k]*BT[b,n,k] + bias[m]*balpha
// CTA 128x128, 8 warps (2x4), warp 64x32. K-chunk 32, double-buffered.
// Smem row stride 40 bf16 (80B) -> conflict-free ldmatrix.
// ---------------------------------------------------------------------------
#define KC 32
#define RS 40                   // row stride in bf16
#define MAT_B (128 * RS * 2)    // 10240 bytes per matrix tile
#define BUF_B (4 * MAT_B)       // Ahi | Alo | Bhi | Blo

__global__ __launch_bounds__(256) void gemm_mma(
    const __nv_bfloat16* __restrict__ Ahi, const __nv_bfloat16* __restrict__ Alo,
    const __nv_bfloat16* __restrict__ Bhi, const __nv_bfloat16* __restrict__ Blo,
    const float* __restrict__ bias, float* __restrict__ Y, float balpha)
{
    extern __shared__ __align__(128) char smem[];

    const int b  = blockIdx.z;
    const int m0 = blockIdx.y * 128;
    const int n0 = blockIdx.x * 128;
    const __nv_bfloat16* Bhi_b = Bhi + (size_t)b * NL * NC;
    const __nv_bfloat16* Blo_b = Blo + (size_t)b * NL * NC;
    float* Yb = Y + (size_t)b * NC * NL;

    const int t = threadIdx.x;
    const int warp = t >> 5, lane = t & 31;
    const int wm = (warp >> 2) * 64;     // warp m-offset in tile
    const int wn = (warp & 3) * 32;      // warp n-offset in tile
    const uint32_t sbase = smem_u32(smem);

    // ldmatrix per-lane address components
    const int a_lr = lane & 15;                          // row within m16
    const int a_hc = (lane >> 4) * 8;                    // col half
    const int b_nr = (lane & 7) + ((lane >> 4) << 3);    // row within n16
    const int b_kc = ((lane >> 3) & 1) * 8;              // col half

    // cp.async mapping: u in [0, 2048): mat(2b) | row(7b) | c16(2b)
    auto load_chunk = [&](int buf, int k0) {
#pragma unroll
        for (int it = 0; it < 8; it++) {
            int u = t + it * 256;
            int mat = u >> 9, rem = u & 511;
            int row = rem >> 2, c16 = rem & 3;
            const __nv_bfloat16* src;
            if (mat == 0)      src = Ahi   + (size_t)(m0 + row) * NC + k0 + c16 * 8;
            else if (mat == 1) src = Alo   + (size_t)(m0 + row) * NC + k0 + c16 * 8;
            else if (mat == 2) src = Bhi_b + (size_t)(n0 + row) * NC + k0 + c16 * 8;
            else               src = Blo_b + (size_t)(n0 + row) * NC + k0 + c16 * 8;
            cp16(sbase + buf * BUF_B + mat * MAT_B + row * (RS * 2) + c16 * 16, src);
        }
        cp_commit();
    };

    float d[4][4][4];
#pragma unroll
    for (int mi = 0; mi < 4; mi++)
#pragma unroll
        for (int ni = 0; ni < 4; ni++)
#pragma unroll
            for (int q = 0; q < 4; q++) d[mi][ni][q] = 0.f;

    load_chunk(0, 0);

    for (int ch = 0; ch < NC / KC; ch++) {
        const int buf = ch & 1;
        if (ch + 1 < NC / KC) { load_chunk(buf ^ 1, (ch + 1) * KC); cp_wait1(); }
        else cp_wait0();
        __syncthreads();

        const uint32_t base  = sbase + buf * BUF_B;
        const uint32_t aHiB  = base;
        const uint32_t aLoB  = base + MAT_B;
        const uint32_t bHiB  = base + 2 * MAT_B;
        const uint32_t bLoB  = base + 3 * MAT_B;

#pragma unroll
        for (int ks = 0; ks < 2; ks++) {
            const int kc = ks * 16;
            uint32_t ah[4][4], al[4][4], bh[4][2], bl[4][2];
#pragma unroll
            for (int mi = 0; mi < 4; mi++) {
                uint32_t r = (wm + mi * 16 + a_lr) * (RS * 2) + (kc + a_hc) * 2;
                ld4(ah[mi], aHiB + r);
                ld4(al[mi], aLoB + r);
            }
#pragma unroll
            for (int pi = 0; pi < 2; pi++) {
                uint32_t r = (wn + pi * 16 + b_nr) * (RS * 2) + (kc + b_kc) * 2;
                uint32_t tmp[4];
                ld4(tmp, bHiB + r);
                bh[2 * pi][0] = tmp[0]; bh[2 * pi][1] = tmp[1];
                bh[2 * pi + 1][0] = tmp[2]; bh[2 * pi + 1][1] = tmp[3];
                ld4(tmp, bLoB + r);
                bl[2 * pi][0] = tmp[0]; bl[2 * pi][1] = tmp[1];
                bl[2 * pi + 1][0] = tmp[2]; bl[2 * pi + 1][1] = tmp[3];
            }
#pragma unroll
            for (int mi = 0; mi < 4; mi++)
#pragma unroll
                for (int ni = 0; ni < 4; ni++) {
                    mma_bf16(d[mi][ni], ah[mi], bh[ni]);
                    mma_bf16(d[mi][ni], ah[mi], bl[ni]);
                    mma_bf16(d[mi][ni], al[mi], bh[ni]);
                }
        }
        __syncthreads();
    }

    // Epilogue: c0,c1 -> (row=lane>>2, col=2*(lane&3)); c2,c3 -> row+8.
    const int erow = lane >> 2, ecol = 2 * (lane & 3);
#pragma unroll
    for (int mi = 0; mi < 4; mi++) {
        int mA = m0 + wm + mi * 16 + erow;
        float bvA = __ldg(bias + mA) * balpha;
        float bvB = __ldg(bias + mA + 8) * balpha;
        float* rowA = Yb + (size_t)mA * NL + n0 + wn + ecol;
        float* rowB = rowA + 8 * NL;
#pragma unroll
        for (int ni = 0; ni < 4; ni++) {
            float2 vA = make_float2(d[mi][ni][0] + bvA, d[mi][ni][1] + bvA);
            float2 vB = make_float2(d[mi][ni][2] + bvB, d[mi][ni][3] + bvB);
            *(float2*)(rowA + ni * 8) = vA;
            *(float2*)(rowB + ni * 8) = vB;
        }
    }
}

// ---------------------------------------------------------------------------
// Flash attention (proven R2 compute; epilogue writes bf16 hi/lo transposed).
// ---------------------------------------------------------------------------
#define KPAD 64
#define VPAD 68
#define PPAD 68

__global__ __launch_bounds__(256, 2) void attn_kernel(
    const float* __restrict__ erk, const float* __restrict__ erv)
{
    extern __shared__ float sm[];
    float* Kb   = sm;                       // 2 * 64*64
    float* Vs   = sm + 8192;                // 64*68
    float* Qs   = Vs + 4352;                // 64*64
    float* Ps   = Qs + 4096;                // 64*68
    float* rq   = Ps + 4352;                // 64*NT
    float* arel = rq + 576;
    float* fsc  = arel + 576;
    float* ervs = fsc + 64;

    const int bh = blockIdx.y;
    const int i0 = blockIdx.x * 64;
    const float* qb = g_q + (size_t)bh * DH * NL;
    const float* kb = g_k + (size_t)bh * DH * NL;
    const float* vb = g_v + (size_t)bh * DH * NL;

    const int t  = threadIdx.x;
    const int tx = t & 15, ty = t >> 4;
    const int r0 = ty * 4, c0 = tx * 4;

#pragma unroll
    for (int it = 0; it < 4; it++) {
        int e = t + it * 256, d = e >> 4, l4 = (e & 15) * 4;
        cp16((uint32_t)__cvta_generic_to_shared(Kb + d * KPAD + l4),
             kb + (size_t)d * NL + l4);
    }
    cp_commit();

#pragma unroll
    for (int it = 0; it < 4; it++) {
        int e = t + it * 256, d = e >> 4, l4 = (e & 15) * 4;
        *(float4*)(Qs + d * KPAD + l4) = *(const float4*)(qb + (size_t)d * NL + i0 + l4);
    }
    for (int e = t; e < NT * DH; e += 256) ervs[e] = erv[e];
    __syncthreads();

    for (int e = t; e < 64 * NT; e += 256) {
        int r = e / NT, tt = e % NT;
        float s = 0.f;
#pragma unroll 16
        for (int d = 0; d < DH; d++) s = fmaf(Qs[d * KPAD + r], erk[tt * DH + d], s);
        rq[e] = s;
        arel[e] = 0.f;
    }

    float m_i[4], l_i[4], o[4][4];
#pragma unroll
    for (int i = 0; i < 4; i++) {
        m_i[i] = -INFINITY; l_i[i] = 0.f;
#pragma unroll
        for (int j = 0; j < 4; j++) o[i][j] = 0.f;
    }

    int buf = 0;
    for (int jt = 0; jt < 16; jt++, buf ^= 1) {
        const int j0 = jt * 64;
        cp_wait0();
        __syncthreads();

        if (jt + 1 < 16) {
            const float* kn = kb + j0 + 64;
#pragma unroll
            for (int it = 0; it < 4; it++) {
                int e = t + it * 256, d = e >> 4, l4 = (e & 15) * 4;
                cp16((uint32_t)__cvta_generic_to_shared(Kb + (buf ^ 1) * 4096 + d * KPAD + l4),
                     kn + (size_t)d * NL + l4);
            }
            cp_commit();
        }

        float vr[4][4];
#pragma unroll
        for (int it = 0; it < 4; it++) {
            int e = t + it * 256, l = e & 63, d4 = (e >> 6) * 4;
            const float* vp = vb + (size_t)d4 * NL + j0 + l;
#pragma unroll
            for (int k = 0; k < 4; k++) vr[it][k] = __ldg(vp + (size_t)k * NL);
        }

        const float* Kt = Kb + buf * 4096;
        float s4[4][4];
#pragma unroll
        for (int i = 0; i < 4; i++)
#pragma unroll
            for (int j = 0; j < 4; j++) s4[i][j] = 0.f;

#pragma unroll 4
        for (int d = 0; d < DH; d++) {
            float4 q = *(const float4*)(Qs + d * KPAD + r0);
            float4 k = *(const float4*)(Kt + d * KPAD + c0);
            s4[0][0] = fmaf(q.x, k.x, s4[0][0]); s4[0][1] = fmaf(q.x, k.y, s4[0][1]);
            s4[0][2] = fmaf(q.x, k.z, s4[0][2]); s4[0][3] = fmaf(q.x, k.w, s4[0][3]);
            s4[1][0] = fmaf(q.y, k.x, s4[1][0]); s4[1][1] = fmaf(q.y, k.y, s4[1][1]);
            s4[1][2] = fmaf(q.y, k.z, s4[1][2]); s4[1][3] = fmaf(q.y, k.w, s4[1][3]);
            s4[2][0] = fmaf(q.z, k.x, s4[2][0]); s4[2][1] = fmaf(q.z, k.y, s4[2][1]);
            s4[2][2] = fmaf(q.z, k.z, s4[2][2]); s4[2][3] = fmaf(q.z, k.w, s4[2][3]);
            s4[3][0] = fmaf(q.w, k.x, s4[3][0]); s4[3][1] = fmaf(q.w, k.y, s4[3][1]);
            s4[3][2] = fmaf(q.w, k.z, s4[3][2]); s4[3][3] = fmaf(q.w, k.w, s4[3][3]);
        }

#pragma unroll
        for (int i = 0; i < 4; i++) {
            int base = (j0 + c0) - (i0 + r0 + i) + WIN;
#pragma unroll
            for (int j = 0; j < 4; j++) {
                int tt = base + j;
                if (tt >= 0 && tt < NT) s4[i][j] += rq[(r0 + i) * NT + tt];
            }
        }

#pragma unroll
        for (int i = 0; i < 4; i++) {
            float mx = fmaxf(fmaxf(s4[i][0], s4[i][1]), fmaxf(s4[i][2], s4[i][3]));
#pragma unroll
            for (int off = 8; off; off >>= 1)
                mx = fmaxf(mx, __shfl_xor_sync(0xffffffffu, mx, off));
            float mnew = fmaxf(m_i[i], mx);
            float f = __expf(m_i[i] - mnew);
            float rs = 0.f;
#pragma unroll
            for (int j = 0; j < 4; j++) { s4[i][j] = __expf(s4[i][j] - mnew); rs += s4[i][j]; }
#pragma unroll
            for (int off = 8; off; off >>= 1)
                rs += __shfl_xor_sync(0xffffffffu, rs, off);
            l_i[i] = l_i[i] * f + rs;
            m_i[i] = mnew;
#pragma unroll
            for (int j = 0; j < 4; j++) o[i][j] *= f;
            if (tx == 0) fsc[r0 + i] = f;
        }

#pragma unroll
        for (int j = 0; j < 4; j++) {
            float4 pj = make_float4(s4[0][j], s4[1][j], s4[2][j], s4[3][j]);
            *(float4*)(Ps + (c0 + j) * PPAD + r0) = pj;
        }

#pragma unroll
        for (int it = 0; it < 4; it++) {
            int e = t + it * 256, l = e & 63, d4 = (e >> 6) * 4;
            *(float4*)(Vs + l * VPAD + d4) =
                make_float4(vr[it][0], vr[it][1], vr[it][2], vr[it][3]);
        }
        __syncthreads();

        for (int e = t; e < 64 * NT; e += 256) {
            int r = e / NT, tt = e % NT;
            int jg = (i0 + r) + tt - WIN;
            float a = arel[e] * fsc[r];
            if (jg >= j0 && jg < j0 + 64) a += Ps[(jg - j0) * PPAD + r];
            arel[e] = a;
        }

#pragma unroll 4
        for (int c = 0; c < 64; c++) {
            float4 p = *(const float4*)(Ps + c * PPAD + r0);
            float4 v = *(const float4*)(Vs + c * VPAD + c0);
            o[0][0] = fmaf(p.x, v.x, o[0][0]); o[0][1] = fmaf(p.x, v.y, o[0][1]);
            o[0][2] = fmaf(p.x, v.z, o[0][2]); o[0][3] = fmaf(p.x, v.w, o[0][3]);
            o[1][0] = fmaf(p.y, v.x, o[1][0]); o[1][1] = fmaf(p.y, v.y, o[1][1]);
            o[1][2] = fmaf(p.y, v.z, o[1][2]); o[1][3] = fmaf(p.y, v.w, o[1][3]);
            o[2][0] = fmaf(p.z, v.x, o[2][0]); o[2][1] = fmaf(p.z, v.y, o[2][1]);
            o[2][2] = fmaf(p.z, v.z, o[2][2]); o[2][3] = fmaf(p.z, v.w, o[2][3]);
            o[3][0] = fmaf(p.w, v.x, o[3][0]); o[3][1] = fmaf(p.w, v.y, o[3][1]);
            o[3][2] = fmaf(p.w, v.z, o[3][2]); o[3][3] = fmaf(p.w, v.w, o[3][3]);
        }
        __syncthreads();
    }

    // Epilogue: O into Vs as [l][d], then bf16 hi/lo store to g_tT[b][l][h*64+d]
#pragma unroll
    for (int i = 0; i < 4; i++) {
        float inv = 1.f / l_i[i];
#pragma unroll
        for (int j = 0; j < 4; j++) {
            float rv = 0.f;
#pragma unroll
            for (int tt = 0; tt < NT; tt++)
                rv = fmaf(arel[(r0 + i) * NT + tt], ervs[tt * DH + c0 + j], rv);
            Vs[(r0 + i) * VPAD + (c0 + j)] = (o[i][j] + rv) * inv;
        }
    }
    __syncthreads();

    const int b = bh >> 3, h = bh & 7;
    __nv_bfloat16* thi = g_tT_hi + ((size_t)b * NL + i0) * NC + h * DH;
    __nv_bfloat16* tlo = g_tT_lo + ((size_t)b * NL + i0) * NC + h * DH;
    for (int e = t; e < 64 * 32; e += 256) {
        int l = e >> 5, d2 = e & 31;
        float v0 = Vs[l * VPAD + 2 * d2], v1 = Vs[l * VPAD + 2 * d2 + 1];
        __nv_bfloat16 h0 = __float2bfloat16(v0);
        __nv_bfloat16 h1 = __float2bfloat16(v1);
        __nv_bfloat162 hp; hp.x = h0; hp.y = h1;
        __nv_bfloat162 lp;
        lp.x = __float2bfloat16(v0 - __bfloat162float(h0));
        lp.y = __float2bfloat16(v1 - __bfloat162float(h1));
        *(__nv_bfloat162*)(thi + (size_t)l * NC + 2 * d2) = hp;
        *(__nv_bfloat162*)(tlo + (size_t)l * NC + 2 * d2) = lp;
    }
}

// ---------------------------------------------------------------------------
extern "C" void kernel_launch(void* const* d_in, const int* in_sizes, int n_in,
                              void* d_out, int out_size)
{
    const float* x   = (const float*)d_in[0];
    const float* Wq  = (const float*)d_in[1];
    const float* bq  = (const float*)d_in[2];
    const float* Wk  = (const float*)d_in[3];
    const float* bk  = (const float*)d_in[4];
    const float* Wv  = (const float*)d_in[5];
    const float* bv  = (const float*)d_in[6];
    const float* Wo  = (const float*)d_in[7];
    const float* bo  = (const float*)d_in[8];
    const float* erk = (const float*)d_in[9];
    const float* erv = (const float*)d_in[10];
    float* out = (float*)d_out;

    float *gq, *gk, *gv;
    __nv_bfloat16 *xh, *xl, *th, *tl, *wh, *wl;
    cudaGetSymbolAddress((void**)&gq, g_q);
    cudaGetSymbolAddress((void**)&gk, g_k);
    cudaGetSymbolAddress((void**)&gv, g_v);
    cudaGetSymbolAddress((void**)&xh, g_xT_hi);
    cudaGetSymbolAddress((void**)&xl, g_xT_lo);
    cudaGetSymbolAddress((void**)&th, g_tT_hi);
    cudaGetSymbolAddress((void**)&tl, g_tT_lo);
    cudaGetSymbolAddress((void**)&wh, g_W_hi);
    cudaGetSymbolAddress((void**)&wl, g_W_lo);

    const int attn_smem = (8192 + 4352 + 4096 + 4352 + 576 + 576 + 64 + 576) * 4;
    const int gemm_smem = 2 * BUF_B;   // 81920
    cudaFuncSetAttribute(attn_kernel,
                         cudaFuncAttributeMaxDynamicSharedMemorySize, attn_smem);
    cudaFuncSetAttribute(gemm_mma,
                         cudaFuncAttributeMaxDynamicSharedMemorySize, gemm_smem);

    split_w<<<dim3(NC * NC / 256, 4), 256>>>(Wq, Wk, Wv, Wo);
    split_xT<<<dim3(NL / 32, NC / 32, NB), 256>>>(x);

    dim3 gg(NL / 128, NC / 128, NB);   // (8,4,8)
    const int WSZ = NC * NC;
    gemm_mma<<<gg, 256, gemm_smem>>>(wh + 0 * WSZ, wl + 0 * WSZ, xh, xl, bq, gq, 0.125f);
    gemm_mma<<<gg, 256, gemm_smem>>>(wh + 1 * WSZ, wl + 1 * WSZ, xh, xl, bk, gk, 1.f);
    gemm_mma<<<gg, 256, gemm_smem>>>(wh + 2 * WSZ, wl + 2 * WSZ, xh, xl, bv, gv, 1.f);

    dim3 ga(NL / 64, NB * NH);
    attn_kernel<<<ga, 256, attn_smem>>>(erk, erv);

    gemm_mma<<<gg, 256, gemm_smem>>>(wh + 3 * WSZ, wl + 3 * WSZ, th, tl, bo, out, 1.f);
}

// round 5
// speedup vs baseline: 2.5034x; 1.7542x over previous
#include <cuda_runtime.h>
#include <cuda_bf16.h>
#include <math.h>
#include <stdint.h>

#define NB 8
#define NC 512
#define NL 1024
#define NH 8
#define DH 64
#define WIN 4
#define NT 9   // 2*WIN+1

// Scratch (allocation-free contract).
__device__ __nv_bfloat16 g_qh[NB * NC * NL];      // q bf16 hi [b][c][l]
__device__ __nv_bfloat16 g_ql[NB * NC * NL];
__device__ __nv_bfloat16 g_kh[NB * NC * NL];
__device__ __nv_bfloat16 g_kl[NB * NC * NL];
__device__ __nv_bfloat16 g_vh[NB * NC * NL];
__device__ __nv_bfloat16 g_vl[NB * NC * NL];
__device__ __nv_bfloat16 g_xT_hi[NB * NL * NC];   // x transposed [b][l][c]
__device__ __nv_bfloat16 g_xT_lo[NB * NL * NC];
__device__ __nv_bfloat16 g_tT_hi[NB * NL * NC];   // attn out transposed [b][l][c]
__device__ __nv_bfloat16 g_tT_lo[NB * NL * NC];
__device__ __nv_bfloat16 g_W_hi[4 * NC * NC];     // Wq*0.125, Wk, Wv, Wo
__device__ __nv_bfloat16 g_W_lo[4 * NC * NC];

// ---------------- PTX helpers (sm_80-portable only) ----------------
__device__ __forceinline__ void cp16(uint32_t dst, const void* src) {
    asm volatile("cp.async.cg.shared.global [%0], [%1], 16;" :: "r"(dst), "l"(src));
}
__device__ __forceinline__ void cp_commit() { asm volatile("cp.async.commit_group;"); }
__device__ __forceinline__ void cp_wait0() { asm volatile("cp.async.wait_group 0;" ::: "memory"); }
__device__ __forceinline__ void cp_wait1() { asm volatile("cp.async.wait_group 1;" ::: "memory"); }

__device__ __forceinline__ uint32_t smem_u32(const void* p) {
    uint32_t a;
    asm("{ .reg .u64 t; cvta.to.shared.u64 t, %1; cvt.u32.u64 %0, t; }" : "=r"(a) : "l"(p));
    return a;
}
__device__ __forceinline__ void ld4(uint32_t* r, uint32_t addr) {
    asm volatile("ldmatrix.sync.aligned.m8n8.x4.shared.b16 {%0,%1,%2,%3}, [%4];"
                 : "=r"(r[0]), "=r"(r[1]), "=r"(r[2]), "=r"(r[3]) : "r"(addr));
}
__device__ __forceinline__ void ld4t(uint32_t* r, uint32_t addr) {
    asm volatile("ldmatrix.sync.aligned.m8n8.x4.trans.shared.b16 {%0,%1,%2,%3}, [%4];"
                 : "=r"(r[0]), "=r"(r[1]), "=r"(r[2]), "=r"(r[3]) : "r"(addr));
}
__device__ __forceinline__ void mma_bf16(float* d, const uint32_t* a, const uint32_t* b) {
    asm volatile(
        "mma.sync.aligned.m16n8k16.row.col.f32.bf16.bf16.f32 "
        "{%0,%1,%2,%3}, {%4,%5,%6,%7}, {%8,%9}, {%0,%1,%2,%3};"
        : "+f"(d[0]), "+f"(d[1]), "+f"(d[2]), "+f"(d[3])
        : "r"(a[0]), "r"(a[1]), "r"(a[2]), "r"(a[3]), "r"(b[0]), "r"(b[1]));
}
__device__ __forceinline__ void split2(float v0, float v1, uint32_t& hi, uint32_t& lo) {
    __nv_bfloat16 h0 = __float2bfloat16(v0), h1 = __float2bfloat16(v1);
    __nv_bfloat162 hp; hp.x = h0; hp.y = h1;
    __nv_bfloat162 lp;
    lp.x = __float2bfloat16(v0 - __bfloat162float(h0));
    lp.y = __float2bfloat16(v1 - __bfloat162float(h1));
    hi = *(uint32_t*)&hp; lo = *(uint32_t*)&lp;
}

// ---------------------------------------------------------------------------
// Prep: split weights / transpose-split x.
// ---------------------------------------------------------------------------
__global__ void split_w(const float* __restrict__ w0, const float* __restrict__ w1,
                        const float* __restrict__ w2, const float* __restrict__ w3)
{
    int widx = blockIdx.y;
    const float* w = widx == 0 ? w0 : widx == 1 ? w1 : widx == 2 ? w2 : w3;
    float alpha = (widx == 0) ? 0.125f : 1.f;
    int e = blockIdx.x * 256 + threadIdx.x;
    float v = w[e] * alpha;
    __nv_bfloat16 hi = __float2bfloat16(v);
    g_W_hi[widx * NC * NC + e] = hi;
    g_W_lo[widx * NC * NC + e] = __float2bfloat16(v - __bfloat162float(hi));
}

__global__ __launch_bounds__(256) void split_xT(const float* __restrict__ x)
{
    __shared__ float tile[32][33];
    int b = blockIdx.z, c0 = blockIdx.y * 32, l0 = blockIdx.x * 32;
    const float* xb = x + ((size_t)b * NC + c0) * NL + l0;
    int tx = threadIdx.x & 31, ty = threadIdx.x >> 5;
#pragma unroll
    for (int i = 0; i < 4; i++)
        tile[ty + i * 8][tx] = xb[(size_t)(ty + i * 8) * NL + tx];
    __syncthreads();
    size_t ob = ((size_t)b * NL + l0) * NC + c0;
#pragma unroll
    for (int i = 0; i < 4; i++) {
        int r = ty + i * 8;
        float v = tile[tx][r];
        __nv_bfloat16 hi = __float2bfloat16(v);
        g_xT_hi[ob + (size_t)r * NC + tx] = hi;
        g_xT_lo[ob + (size_t)r * NC + tx] = __float2bfloat16(v - __bfloat162float(hi));
    }
}

// ---------------------------------------------------------------------------
// mma.sync bf16x2 GEMM. BF16OUT: write hi/lo bf16 pair (QKV). Else fp32 Y.
// ---------------------------------------------------------------------------
#define KC 32
#define RS 40
#define MAT_B (128 * RS * 2)
#define BUF_B (4 * MAT_B)

template<bool BF16OUT>
__global__ __launch_bounds__(256) void gemm_mma(
    const __nv_bfloat16* __restrict__ Ahi, const __nv_bfloat16* __restrict__ Alo,
    const __nv_bfloat16* __restrict__ Bhi, const __nv_bfloat16* __restrict__ Blo,
    const float* __restrict__ bias, float* __restrict__ Y,
    __nv_bfloat16* __restrict__ Yh, __nv_bfloat16* __restrict__ Yl, float balpha)
{
    extern __shared__ __align__(128) char smem[];

    const int b  = blockIdx.z;
    const int m0 = blockIdx.y * 128;
    const int n0 = blockIdx.x * 128;
    const __nv_bfloat16* Bhi_b = Bhi + (size_t)b * NL * NC;
    const __nv_bfloat16* Blo_b = Blo + (size_t)b * NL * NC;

    const int t = threadIdx.x;
    const int warp = t >> 5, lane = t & 31;
    const int wm = (warp >> 2) * 64;
    const int wn = (warp & 3) * 32;
    const uint32_t sbase = smem_u32(smem);

    const int a_lr = lane & 15;
    const int a_hc = (lane >> 4) * 8;
    const int b_nr = (lane & 7) + ((lane >> 4) << 3);
    const int b_kc = ((lane >> 3) & 1) * 8;

    auto load_chunk = [&](int buf, int k0) {
#pragma unroll
        for (int it = 0; it < 8; it++) {
            int u = t + it * 256;
            int mat = u >> 9, rem = u & 511;
            int row = rem >> 2, c16 = rem & 3;
            const __nv_bfloat16* src;
            if (mat == 0)      src = Ahi   + (size_t)(m0 + row) * NC + k0 + c16 * 8;
            else if (mat == 1) src = Alo   + (size_t)(m0 + row) * NC + k0 + c16 * 8;
            else if (mat == 2) src = Bhi_b + (size_t)(n0 + row) * NC + k0 + c16 * 8;
            else               src = Blo_b + (size_t)(n0 + row) * NC + k0 + c16 * 8;
            cp16(sbase + buf * BUF_B + mat * MAT_B + row * (RS * 2) + c16 * 16, src);
        }
        cp_commit();
    };

    float d[4][4][4];
#pragma unroll
    for (int mi = 0; mi < 4; mi++)
#pragma unroll
        for (int ni = 0; ni < 4; ni++)
#pragma unroll
            for (int q = 0; q < 4; q++) d[mi][ni][q] = 0.f;

    load_chunk(0, 0);

    for (int ch = 0; ch < NC / KC; ch++) {
        const int buf = ch & 1;
        if (ch + 1 < NC / KC) { load_chunk(buf ^ 1, (ch + 1) * KC); cp_wait1(); }
        else cp_wait0();
        __syncthreads();

        const uint32_t base = sbase + buf * BUF_B;
#pragma unroll
        for (int ks = 0; ks < 2; ks++) {
            const int kc = ks * 16;
            uint32_t ah[4][4], al[4][4], bh[4][2], bl[4][2];
#pragma unroll
            for (int mi = 0; mi < 4; mi++) {
                uint32_t r = (wm + mi * 16 + a_lr) * (RS * 2) + (kc + a_hc) * 2;
                ld4(ah[mi], base + r);
                ld4(al[mi], base + MAT_B + r);
            }
#pragma unroll
            for (int pi = 0; pi < 2; pi++) {
                uint32_t r = (wn + pi * 16 + b_nr) * (RS * 2) + (kc + b_kc) * 2;
                uint32_t tmp[4];
                ld4(tmp, base + 2 * MAT_B + r);
                bh[2 * pi][0] = tmp[0]; bh[2 * pi][1] = tmp[1];
                bh[2 * pi + 1][0] = tmp[2]; bh[2 * pi + 1][1] = tmp[3];
                ld4(tmp, base + 3 * MAT_B + r);
                bl[2 * pi][0] = tmp[0]; bl[2 * pi][1] = tmp[1];
                bl[2 * pi + 1][0] = tmp[2]; bl[2 * pi + 1][1] = tmp[3];
            }
#pragma unroll
            for (int mi = 0; mi < 4; mi++)
#pragma unroll
                for (int ni = 0; ni < 4; ni++) {
                    mma_bf16(d[mi][ni], ah[mi], bh[ni]);
                    mma_bf16(d[mi][ni], ah[mi], bl[ni]);
                    mma_bf16(d[mi][ni], al[mi], bh[ni]);
                }
        }
        __syncthreads();
    }

    const int erow = lane >> 2, ecol = 2 * (lane & 3);
#pragma unroll
    for (int mi = 0; mi < 4; mi++) {
        int mA = m0 + wm + mi * 16 + erow;
        float bvA = __ldg(bias + mA) * balpha;
        float bvB = __ldg(bias + mA + 8) * balpha;
        if (BF16OUT) {
            __nv_bfloat16* ohA = Yh + ((size_t)b * NC + mA) * NL + n0 + wn + ecol;
            __nv_bfloat16* olA = Yl + ((size_t)b * NC + mA) * NL + n0 + wn + ecol;
            __nv_bfloat16* ohB = ohA + 8 * NL;
            __nv_bfloat16* olB = olA + 8 * NL;
#pragma unroll
            for (int ni = 0; ni < 4; ni++) {
                uint32_t hA, lA, hB, lB;
                split2(d[mi][ni][0] + bvA, d[mi][ni][1] + bvA, hA, lA);
                split2(d[mi][ni][2] + bvB, d[mi][ni][3] + bvB, hB, lB);
                *(uint32_t*)(ohA + ni * 8) = hA; *(uint32_t*)(olA + ni * 8) = lA;
                *(uint32_t*)(ohB + ni * 8) = hB; *(uint32_t*)(olB + ni * 8) = lB;
            }
        } else {
            float* rowA = Y + (size_t)b * NC * NL + (size_t)mA * NL + n0 + wn + ecol;
            float* rowB = rowA + 8 * NL;
#pragma unroll
            for (int ni = 0; ni < 4; ni++) {
                *(float2*)(rowA + ni * 8) = make_float2(d[mi][ni][0] + bvA, d[mi][ni][1] + bvA);
                *(float2*)(rowB + ni * 8) = make_float2(d[mi][ni][2] + bvB, d[mi][ni][3] + bvB);
            }
        }
    }
}

// ---------------------------------------------------------------------------
// Tensor-core flash attention. 64x64 tiles, bf16 hi/lo 3-term MMAs, P reused
// in registers, band-limited rel terms. 128 threads (4 warps), 2 CTA/SM.
// Smem tiles [d][l] pitch 72 bf16 (conflict-free ldmatrix).
// ---------------------------------------------------------------------------
#define P72 72
#define TILB (64 * P72 * 2)   // 9216 bytes per matrix tile
#define OQH 0
#define OQL (TILB)
#define OKH (2 * TILB)
#define OKL (4 * TILB)
#define OVH (6 * TILB)
#define OVL (8 * TILB)
#define OF32 (10 * TILB)      // 92160: rq | arel | ervs (each 576 floats)
#define ATTN_SMEM (OF32 + 3 * 576 * 4)

__global__ __launch_bounds__(128, 2) void attn_tc(
    const float* __restrict__ erk, const float* __restrict__ erv)
{
    extern __shared__ __align__(128) char sm[];
    const uint32_t sb = smem_u32(sm);
    float* rqs  = (float*)(sm + OF32);
    float* arel = rqs + 576;
    float* ervs = arel + 576;

    const int bh = blockIdx.y, b = bh >> 3, h = bh & 7;
    const int i0 = blockIdx.x * 64;
    const size_t gb = ((size_t)b * NC + h * DH) * NL;
    const __nv_bfloat16* gq[2] = {g_qh + gb, g_ql + gb};
    const __nv_bfloat16* gkv[4] = {g_kh + gb, g_kl + gb, g_vh + gb, g_vl + gb};

    const int t = threadIdx.x, lane = t & 31, w = t >> 5;
    const int lr = lane >> 2, lc = 2 * (lane & 3);

    // ldmatrix per-lane offsets
    const int qrow = (lane & 7) + ((lane >> 4) & 1) * 8, qcol = ((lane >> 3) & 1) * 8;
    const int krow = (lane & 7) + ((lane >> 3) & 1) * 8, kcol = ((lane >> 4) & 1) * 8;
    const int vrow = (lane & 7) + ((lane >> 4) & 1) * 8, vcol = ((lane >> 3) & 1) * 8;

    // ---- Q tiles (hi+lo): 1024 x 16B chunks ----
#pragma unroll
    for (int it = 0; it < 8; it++) {
        int e = t + it * 128;
        int mat = e >> 9, rem = e & 511, row = rem >> 3, c16 = rem & 7;
        cp16(sb + (mat ? OQL : OQH) + row * (P72 * 2) + c16 * 16,
             gq[mat] + (size_t)row * NL + i0 + c16 * 8);
    }
    cp_commit();

    auto issue_kv = [&](int buf, int j0g) {
#pragma unroll
        for (int it = 0; it < 16; it++) {
            int e = t + it * 128;
            int mat = e >> 9, rem = e & 511, row = rem >> 3, c16 = rem & 7;
            uint32_t off = (mat == 0 ? OKH : mat == 1 ? OKL : mat == 2 ? OVH : OVL);
            cp16(sb + off + buf * TILB + row * (P72 * 2) + c16 * 16,
                 gkv[mat] + (size_t)row * NL + j0g + c16 * 8);
        }
        cp_commit();
    };
    issue_kv(0, 0);

    for (int e = t; e < NT * DH; e += 128) ervs[e] = erv[e];

    cp_wait1();          // Q done (KV0 may pend)
    __syncthreads();

    // rq[r][tt] = sum_d (qh+ql)[d][r] * erk[tt][d] ; arel = 0
    {
        const __nv_bfloat16* qsh = (const __nv_bfloat16*)(sm + OQH);
        const __nv_bfloat16* qsl = (const __nv_bfloat16*)(sm + OQL);
        for (int e = t; e < 64 * NT; e += 128) {
            int r = e / NT, tt = e % NT;
            float s = 0.f;
#pragma unroll 16
            for (int d = 0; d < DH; d++)
                s = fmaf(__bfloat162float(qsh[d * P72 + r]) + __bfloat162float(qsl[d * P72 + r]),
                         erk[tt * DH + d], s);
            rqs[e] = s;
            arel[e] = 0.f;
        }
    }

    // Q fragments (persistent)
    uint32_t qhf[4][4], qlf[4][4];
#pragma unroll
    for (int kc = 0; kc < 4; kc++) {
        uint32_t r = ((kc * 16 + qrow) * P72 + 16 * w + qcol) * 2;
        ld4t(qhf[kc], sb + OQH + r);
        ld4t(qlf[kc], sb + OQL + r);
    }
    __syncthreads();   // rq ready for all

    float m0 = -INFINITY, m1 = -INFINITY, l0 = 0.f, l1 = 0.f;
    float o[8][4];
#pragma unroll
    for (int sbk = 0; sbk < 8; sbk++)
#pragma unroll
        for (int q = 0; q < 4; q++) o[sbk][q] = 0.f;

    const int iloc0 = 16 * w + lr, iloc1 = iloc0 + 8;

    for (int jt = 0; jt < 16; jt++) {
        const int j0 = jt * 64;
        const int buf = jt & 1;
        const bool band = (j0 - i0 <= 64) && (i0 - j0 <= 64);

        __syncthreads();   // all warps done with buf^1 (prev-prev tile)
        if (jt + 1 < 16) { issue_kv(buf ^ 1, j0 + 64); cp_wait1(); }
        else cp_wait0();
        __syncthreads();   // KV[jt] visible to all

        // ---- S = Q K^T ----
        float s[8][4];
#pragma unroll
        for (int sbk = 0; sbk < 8; sbk++)
#pragma unroll
            for (int q = 0; q < 4; q++) s[sbk][q] = 0.f;

        const uint32_t kh_b = sb + OKH + buf * TILB, kl_b = sb + OKL + buf * TILB;
#pragma unroll
        for (int nb = 0; nb < 4; nb++) {
#pragma unroll
            for (int kc = 0; kc < 4; kc++) {
                uint32_t r = ((kc * 16 + krow) * P72 + nb * 16 + kcol) * 2;
                uint32_t kh4[4], kl4[4];
                ld4t(kh4, kh_b + r);
                ld4t(kl4, kl_b + r);
                mma_bf16(s[2 * nb],     qhf[kc], kh4);
                mma_bf16(s[2 * nb],     qhf[kc], kl4);
                mma_bf16(s[2 * nb],     qlf[kc], kh4);
                mma_bf16(s[2 * nb + 1], qhf[kc], kh4 + 2);
                mma_bf16(s[2 * nb + 1], qhf[kc], kl4 + 2);
                mma_bf16(s[2 * nb + 1], qlf[kc], kh4 + 2);
            }
        }

        // ---- rel_k band add ----
        if (band) {
#pragma unroll
            for (int sbk = 0; sbk < 8; sbk++) {
                int jg = j0 + sbk * 8 + lc;
                int t00 = jg - (i0 + iloc0) + WIN;
                int t10 = jg - (i0 + iloc1) + WIN;
                if (t00 >= 0 && t00 < NT)     s[sbk][0] += rqs[iloc0 * NT + t00];
                if (t00 + 1 >= 0 && t00 + 1 < NT) s[sbk][1] += rqs[iloc0 * NT + t00 + 1];
                if (t10 >= 0 && t10 < NT)     s[sbk][2] += rqs[iloc1 * NT + t10];
                if (t10 + 1 >= 0 && t10 + 1 < NT) s[sbk][3] += rqs[iloc1 * NT + t10 + 1];
            }
        }

        // ---- online softmax ----
        float mx0 = -INFINITY, mx1 = -INFINITY;
#pragma unroll
        for (int sbk = 0; sbk < 8; sbk++) {
            mx0 = fmaxf(mx0, fmaxf(s[sbk][0], s[sbk][1]));
            mx1 = fmaxf(mx1, fmaxf(s[sbk][2], s[sbk][3]));
        }
        mx0 = fmaxf(mx0, __shfl_xor_sync(0xffffffffu, mx0, 1));
        mx0 = fmaxf(mx0, __shfl_xor_sync(0xffffffffu, mx0, 2));
        mx1 = fmaxf(mx1, __shfl_xor_sync(0xffffffffu, mx1, 1));
        mx1 = fmaxf(mx1, __shfl_xor_sync(0xffffffffu, mx1, 2));
        float mn0 = fmaxf(m0, mx0), mn1 = fmaxf(m1, mx1);
        float f0 = __expf(m0 - mn0), f1 = __expf(m1 - mn1);
        float rs0 = 0.f, rs1 = 0.f;
#pragma unroll
        for (int sbk = 0; sbk < 8; sbk++) {
            s[sbk][0] = __expf(s[sbk][0] - mn0); rs0 += s[sbk][0];
            s[sbk][1] = __expf(s[sbk][1] - mn0); rs0 += s[sbk][1];
            s[sbk][2] = __expf(s[sbk][2] - mn1); rs1 += s[sbk][2];
            s[sbk][3] = __expf(s[sbk][3] - mn1); rs1 += s[sbk][3];
        }
        rs0 += __shfl_xor_sync(0xffffffffu, rs0, 1);
        rs0 += __shfl_xor_sync(0xffffffffu, rs0, 2);
        rs1 += __shfl_xor_sync(0xffffffffu, rs1, 1);
        rs1 += __shfl_xor_sync(0xffffffffu, rs1, 2);
        l0 = l0 * f0 + rs0; m0 = mn0;
        l1 = l1 * f1 + rs1; m1 = mn1;
#pragma unroll
        for (int sbk = 0; sbk < 8; sbk++) {
            o[sbk][0] *= f0; o[sbk][1] *= f0; o[sbk][2] *= f1; o[sbk][3] *= f1;
        }

        // ---- arel: scale (warp-private rows), then band add ----
        if ((lane & 3) == 0) {
#pragma unroll
            for (int tt = 0; tt < NT; tt++) {
                arel[iloc0 * NT + tt] *= f0;
                arel[iloc1 * NT + tt] *= f1;
            }
        }
        __syncwarp();
        if (band) {
#pragma unroll
            for (int sbk = 0; sbk < 8; sbk++) {
                int jg = j0 + sbk * 8 + lc;
                int t00 = jg - (i0 + iloc0) + WIN;
                int t10 = jg - (i0 + iloc1) + WIN;
                if (t00 >= 0 && t00 < NT)     arel[iloc0 * NT + t00]     += s[sbk][0];
                if (t00 + 1 >= 0 && t00 + 1 < NT) arel[iloc0 * NT + t00 + 1] += s[sbk][1];
                if (t10 >= 0 && t10 < NT)     arel[iloc1 * NT + t10]     += s[sbk][2];
                if (t10 + 1 >= 0 && t10 + 1 < NT) arel[iloc1 * NT + t10 + 1] += s[sbk][3];
            }
            __syncwarp();
        }

        // ---- pack P (hi/lo) into A fragments ----
        uint32_t pha[4][4], pla[4][4];
#pragma unroll
        for (int kc = 0; kc < 4; kc++) {
            split2(s[2 * kc][0],     s[2 * kc][1],     pha[kc][0], pla[kc][0]);
            split2(s[2 * kc][2],     s[2 * kc][3],     pha[kc][1], pla[kc][1]);
            split2(s[2 * kc + 1][0], s[2 * kc + 1][1], pha[kc][2], pla[kc][2]);
            split2(s[2 * kc + 1][2], s[2 * kc + 1][3], pha[kc][3], pla[kc][3]);
        }

        // ---- O += P V ----
        const uint32_t vh_b = sb + OVH + buf * TILB, vl_b = sb + OVL + buf * TILB;
#pragma unroll
        for (int nb = 0; nb < 4; nb++) {
#pragma unroll
            for (int kc = 0; kc < 4; kc++) {
                uint32_t r = ((nb * 16 + vrow) * P72 + kc * 16 + vcol) * 2;
                uint32_t vh4[4], vl4[4];
                ld4(vh4, vh_b + r);
                ld4(vl4, vl_b + r);
                mma_bf16(o[2 * nb],     pha[kc], vh4);
                mma_bf16(o[2 * nb],     pha[kc], vl4);
                mma_bf16(o[2 * nb],     pla[kc], vh4);
                mma_bf16(o[2 * nb + 1], pha[kc], vh4 + 2);
                mma_bf16(o[2 * nb + 1], pha[kc], vl4 + 2);
                mma_bf16(o[2 * nb + 1], pla[kc], vh4 + 2);
            }
        }
    }

    // ---- epilogue: out = (o + arel*erv) / l ; write bf16 hi/lo to g_tT ----
    float inv0 = 1.f / l0, inv1 = 1.f / l1;
    float ar0[NT], ar1[NT];
#pragma unroll
    for (int tt = 0; tt < NT; tt++) {
        ar0[tt] = arel[iloc0 * NT + tt];
        ar1[tt] = arel[iloc1 * NT + tt];
    }
    __nv_bfloat16* th0 = g_tT_hi + ((size_t)b * NL + i0 + iloc0) * NC + h * DH;
    __nv_bfloat16* tl0 = g_tT_lo + ((size_t)b * NL + i0 + iloc0) * NC + h * DH;
    __nv_bfloat16* th1 = th0 + (size_t)8 * NC;
    __nv_bfloat16* tl1 = tl0 + (size_t)8 * NC;
#pragma unroll
    for (int sbk = 0; sbk < 8; sbk++) {
        int d0 = sbk * 8 + lc;
        float r00 = 0.f, r01 = 0.f, r10 = 0.f, r11 = 0.f;
#pragma unroll
        for (int tt = 0; tt < NT; tt++) {
            float e0 = ervs[tt * DH + d0], e1 = ervs[tt * DH + d0 + 1];
            r00 = fmaf(ar0[tt], e0, r00); r01 = fmaf(ar0[tt], e1, r01);
            r10 = fmaf(ar1[tt], e0, r10); r11 = fmaf(ar1[tt], e1, r11);
        }
        uint32_t hA, lA, hB, lB;
        split2((o[sbk][0] + r00) * inv0, (o[sbk][1] + r01) * inv0, hA, lA);
        split2((o[sbk][2] + r10) * inv1, (o[sbk][3] + r11) * inv1, hB, lB);
        *(uint32_t*)(th0 + d0) = hA; *(uint32_t*)(tl0 + d0) = lA;
        *(uint32_t*)(th1 + d0) = hB; *(uint32_t*)(tl1 + d0) = lB;
    }
}

// ---------------------------------------------------------------------------
extern "C" void kernel_launch(void* const* d_in, const int* in_sizes, int n_in,
                              void* d_out, int out_size)
{
    const float* x   = (const float*)d_in[0];
    const float* Wq  = (const float*)d_in[1];
    const float* bq  = (const float*)d_in[2];
    const float* Wk  = (const float*)d_in[3];
    const float* bk  = (const float*)d_in[4];
    const float* Wv  = (const float*)d_in[5];
    const float* bv  = (const float*)d_in[6];
    const float* Wo  = (const float*)d_in[7];
    const float* bo  = (const float*)d_in[8];
    const float* erk = (const float*)d_in[9];
    const float* erv = (const float*)d_in[10];
    float* out = (float*)d_out;

    __nv_bfloat16 *qh, *ql, *kh, *kl, *vh, *vl, *xh, *xl, *th, *tl, *wh, *wl;
    cudaGetSymbolAddress((void**)&qh, g_qh);
    cudaGetSymbolAddress((void**)&ql, g_ql);
    cudaGetSymbolAddress((void**)&kh, g_kh);
    cudaGetSymbolAddress((void**)&kl, g_kl);
    cudaGetSymbolAddress((void**)&vh, g_vh);
    cudaGetSymbolAddress((void**)&vl, g_vl);
    cudaGetSymbolAddress((void**)&xh, g_xT_hi);
    cudaGetSymbolAddress((void**)&xl, g_xT_lo);
    cudaGetSymbolAddress((void**)&th, g_tT_hi);
    cudaGetSymbolAddress((void**)&tl, g_tT_lo);
    cudaGetSymbolAddress((void**)&wh, g_W_hi);
    cudaGetSymbolAddress((void**)&wl, g_W_lo);

    const int gemm_smem = 2 * BUF_B;
    cudaFuncSetAttribute(gemm_mma<true>,
                         cudaFuncAttributeMaxDynamicSharedMemorySize, gemm_smem);
    cudaFuncSetAttribute(gemm_mma<false>,
                         cudaFuncAttributeMaxDynamicSharedMemorySize, gemm_smem);
    cudaFuncSetAttribute(attn_tc,
                         cudaFuncAttributeMaxDynamicSharedMemorySize, ATTN_SMEM);

    split_w<<<dim3(NC * NC / 256, 4), 256>>>(Wq, Wk, Wv, Wo);
    split_xT<<<dim3(NL / 32, NC / 32, NB), 256>>>(x);

    dim3 gg(NL / 128, NC / 128, NB);
    const int WSZ = NC * NC;
    gemm_mma<true><<<gg, 256, gemm_smem>>>(wh + 0 * WSZ, wl + 0 * WSZ, xh, xl, bq,
                                           nullptr, qh, ql, 0.125f);
    gemm_mma<true><<<gg, 256, gemm_smem>>>(wh + 1 * WSZ, wl + 1 * WSZ, xh, xl, bk,
                                           nullptr, kh, kl, 1.f);
    gemm_mma<true><<<gg, 256, gemm_smem>>>(wh + 2 * WSZ, wl + 2 * WSZ, xh, xl, bv,
                                           nullptr, vh, vl, 1.f);

    dim3 ga(NL / 64, NB * NH);
    attn_tc<<<ga, 128, ATTN_SMEM>>>(erk, erv);

    gemm_mma<false><<<gg, 256, gemm_smem>>>(wh + 3 * WSZ, wl + 3 * WSZ, th, tl, bo,
                                            out, nullptr, nullptr, 1.f);
}